// round 4
// baseline (speedup 1.0000x reference)
#include <cuda_runtime.h>

#define HH   352
#define WW   352
#define NIMG 8
#define TILE 32
#define HALO 5
#define SW   (TILE + 2*HALO)   // 42
#define ALPHA_LOG2E (-288.53900817779268f)  // -200 * log2(e)

// Scratch accumulators: [0] = sum(loss_map*mask), [1] = sum(mask)
__device__ float g_acc[2];

__global__ void btm_init_kernel() {
    g_acc[0] = 0.0f;
    g_acc[1] = 0.0f;
}

__device__ __forceinline__ float fast_exp2(float x) {
    float r;
    asm("ex2.approx.f32 %0, %1;" : "=f"(r) : "f"(x));
    return r;
}

__global__ __launch_bounds__(256, 4)
void btm_main_kernel(const float* __restrict__ pred,
                     const float* __restrict__ feat) {
    // float4 tile: (r, g, b, sal), zero-padded halo of 5
    __shared__ float4 sm[SW * SW];

    const int n  = blockIdx.z;
    const int x0 = blockIdx.x * TILE;
    const int y0 = blockIdx.y * TILE;
    const float* pn = pred + (size_t)n * HH * WW;
    const float* fn = feat + (size_t)n * 3 * HH * WW;

    const int tid = threadIdx.y * 32 + threadIdx.x;

    // Cooperative tile load (coalesced per plane), zero halo for OOB
    for (int i = tid; i < SW * SW; i += 256) {
        int sy = i / SW;
        int sx = i - sy * SW;
        int gy = y0 + sy - HALO;
        int gx = x0 + sx - HALO;
        float4 v = make_float4(0.f, 0.f, 0.f, 0.f);
        if (gy >= 0 && gy < HH && gx >= 0 && gx < WW) {
            int off = gy * WW + gx;
            v.x = fn[off];
            v.y = fn[HH * WW + off];
            v.z = fn[2 * HH * WW + off];
            v.w = pn[off];
        }
        sm[i] = v;
    }
    __syncthreads();

    float loss_t = 0.f;
    float mask_t = 0.f;
    const int lx = threadIdx.x;

    #pragma unroll
    for (int k = 0; k < 4; k++) {
        const int ly = threadIdx.y + 8 * k;
        const int gy = y0 + ly;
        const int gx = x0 + lx;
        const float4* base = &sm[ly * SW + lx];
        const float4 c = base[HALO * SW + HALO];

        // ---- mask: dil - ero over valid 5x5 window of lbl=(sal>0.5) ----
        // reduce_window pads with -inf => OOB taps are EXCLUDED from both
        // the max (dil) and min (ero) pools. Center tap is always valid,
        // so init max=0 / min=1 is exact for binary lbl.
        float vmax = 0.f, vmin = 1.f;
        #pragma unroll
        for (int dy = -2; dy <= 2; dy++) {
            int yy = gy + dy;
            if (yy < 0 || yy >= HH) continue;
            #pragma unroll
            for (int dx = -2; dx <= 2; dx++) {
                int xx = gx + dx;
                if (xx < 0 || xx >= WW) continue;
                float s = base[(HALO + dy) * SW + (HALO + dx)].w;
                float l = (s > 0.5f) ? 1.f : 0.f;
                vmax = fmaxf(vmax, l);
                vmin = fminf(vmin, l);
            }
        }
        const float mask = vmax - vmin;

        // ---- 11x11 bilateral accumulation (zero-padded halo == jnp.pad) ----
        float acc = 0.f;
        #pragma unroll 1
        for (int dy = 0; dy < 11; dy++) {
            const float4* row = base + dy * SW;
            #pragma unroll
            for (int dx = 0; dx < 11; dx++) {
                float4 w = row[dx];
                float dr = w.x - c.x;
                float dg = w.y - c.y;
                float db = w.z - c.z;
                float s  = fmaf(dr, dr, fmaf(dg, dg, db * db));
                float wgt = fast_exp2(s * ALPHA_LOG2E);   // exp(-200*s)
                acc = fmaf(wgt, fabsf(w.w - c.w), acc);
            }
        }

        loss_t += mask * acc;
        mask_t += mask;
    }

    // ---- block reduction: warp shuffle -> smem -> 2 atomics ----
    #pragma unroll
    for (int off = 16; off > 0; off >>= 1) {
        loss_t += __shfl_xor_sync(0xffffffffu, loss_t, off);
        mask_t += __shfl_xor_sync(0xffffffffu, mask_t, off);
    }
    __shared__ float red[16];
    const int wid = tid >> 5;
    const int lid = tid & 31;
    if (lid == 0) {
        red[wid]     = loss_t;
        red[8 + wid] = mask_t;
    }
    __syncthreads();
    if (tid == 0) {
        float L = 0.f, M = 0.f;
        #pragma unroll
        for (int i = 0; i < 8; i++) { L += red[i]; M += red[8 + i]; }
        atomicAdd(&g_acc[0], L);
        atomicAdd(&g_acc[1], M);
    }
}

__global__ void btm_finalize_kernel(float* __restrict__ out) {
    out[0] = g_acc[0] / (g_acc[1] + 1e-6f);
}

extern "C" void kernel_launch(void* const* d_in, const int* in_sizes, int n_in,
                              void* d_out, int out_size) {
    const float* pred = (const float*)d_in[0];   // (8,1,352,352)
    const float* feat = (const float*)d_in[1];   // (8,3,352,352)
    float* out = (float*)d_out;                  // scalar

    btm_init_kernel<<<1, 1>>>();

    dim3 grid(WW / TILE, HH / TILE, NIMG);       // (11, 11, 8)
    dim3 block(32, 8);
    btm_main_kernel<<<grid, block>>>(pred, feat);

    btm_finalize_kernel<<<1, 1>>>(out);
}

// round 7
// speedup vs baseline: 1.2526x; 1.2526x over previous
#include <cuda_runtime.h>

#define HH   352
#define WW   352
#define NIMG 8
#define TILE 32
#define HALO 5
#define SW   (TILE + 2*HALO)            // 42
#define AL2E (-288.53900817779268f)     // -200 * log2(e)
#define C2M  (577.07801635558536f)      // -2 * AL2E

// Scratch accumulators: [0] = sum(loss_map*mask), [1] = sum(mask)
__device__ float g_acc[2];

__global__ void btm_init_kernel() {
    g_acc[0] = 0.0f;
    g_acc[1] = 0.0f;
}

__device__ __forceinline__ float fast_exp2(float x) {
    float r;
    asm("ex2.approx.f32 %0, %1;" : "=f"(r) : "f"(x));
    return r;
}

// Process one smem row: taps (sy, dx=0..10) feeding outputs o in [OLO, OHI].
// e = qA_w + qA_c + w·c2  ==  -alpha*log2e*||w-c||^2   (exponent for ex2)
#define ROW(SY, OLO, OHI) {                                                   \
    const float4* srow = &sm[(ly0 + (SY)) * SW + lx];                         \
    const float*  arow = &ssal[(ly0 + (SY)) * SW + lx];                       \
    _Pragma("unroll")                                                         \
    for (int dx = 0; dx < 11; dx++) {                                         \
        float4 w  = srow[dx];                                                 \
        float  ws = arow[dx];                                                 \
        _Pragma("unroll")                                                     \
        for (int o = (OLO); o <= (OHI); o++) {                                \
            float e = fmaf(w.x, c2x[o],                                       \
                      fmaf(w.y, c2y[o],                                       \
                      fmaf(w.z, c2z[o], w.w + qac[o])));                      \
            acc[o] = fmaf(fast_exp2(e), fabsf(ws - csal[o]), acc[o]);         \
        }                                                                     \
    } }

__global__ __launch_bounds__(256)
void btm_main_kernel(const float* __restrict__ pred,
                     const float* __restrict__ feat) {
    // float4 tile: (r, g, b, AL2E*||rgb||^2), zero-padded halo of 5
    __shared__ float4 sm[SW * SW];
    __shared__ float  ssal[SW * SW];

    const int n  = blockIdx.z;
    const int x0 = blockIdx.x * TILE;
    const int y0 = blockIdx.y * TILE;
    const float* pn = pred + (size_t)n * HH * WW;
    const float* fn = feat + (size_t)n * 3 * HH * WW;

    const int tid = threadIdx.y * 32 + threadIdx.x;

    // Cooperative tile load (coalesced per plane), zero halo for OOB.
    // Zero rgb => qA = 0 and sal = 0, exactly reproducing jnp.pad semantics.
    for (int i = tid; i < SW * SW; i += 256) {
        int sy = i / SW;
        int sx = i - sy * SW;
        int gy = y0 + sy - HALO;
        int gx = x0 + sx - HALO;
        float r = 0.f, g = 0.f, b = 0.f, s = 0.f;
        if (gy >= 0 && gy < HH && gx >= 0 && gx < WW) {
            int off = gy * WW + gx;
            r = fn[off];
            g = fn[HH * WW + off];
            b = fn[2 * HH * WW + off];
            s = pn[off];
        }
        sm[i]   = make_float4(r, g, b, AL2E * fmaf(r, r, fmaf(g, g, b * b)));
        ssal[i] = s;
    }
    __syncthreads();

    const int lx  = threadIdx.x;
    const int ly0 = threadIdx.y * 4;     // 4 CONSECUTIVE output rows per thread

    // ---- mask: dil - ero over valid 5x5 window of lbl=(sal>0.5) ----
    // Row-factored: 8 row-pools shared by the 4 outputs. reduce_window pads
    // with -inf => OOB taps EXCLUDED; center always valid, so neutral
    // (max<-0, min<-1) init is exact for binary lbl.
    float mask[4];
    {
        float rmx[8], rmn[8];
        #pragma unroll
        for (int r8 = 0; r8 < 8; r8++) {
            int gy = y0 + ly0 - 2 + r8;
            float mx = 0.f, mn = 1.f;
            if (gy >= 0 && gy < HH) {
                const float* arow = &ssal[(ly0 + r8 + HALO - 2) * SW + lx + HALO];
                #pragma unroll
                for (int dx = -2; dx <= 2; dx++) {
                    int gxx = x0 + lx + dx;
                    if (gxx >= 0 && gxx < WW) {
                        float l = (arow[dx] > 0.5f) ? 1.f : 0.f;
                        mx = fmaxf(mx, l);
                        mn = fminf(mn, l);
                    }
                }
            }
            rmx[r8] = mx;
            rmn[r8] = mn;
        }
        #pragma unroll
        for (int o = 0; o < 4; o++) {
            float vmx = 0.f, vmn = 1.f;
            #pragma unroll
            for (int k = 0; k < 5; k++) {
                vmx = fmaxf(vmx, rmx[o + k]);
                vmn = fminf(vmn, rmn[o + k]);
            }
            mask[o] = vmx - vmn;
        }
    }

    // ---- per-output center constants (dot-product form, scales pre-folded) ----
    float c2x[4], c2y[4], c2z[4], qac[4], csal[4], acc[4];
    #pragma unroll
    for (int o = 0; o < 4; o++) {
        int ci = (ly0 + o + HALO) * SW + lx + HALO;
        float4 c = sm[ci];
        c2x[o]  = C2M * c.x;
        c2y[o]  = C2M * c.y;
        c2z[o]  = C2M * c.z;
        qac[o]  = c.w;            // AL2E * ||c_rgb||^2
        csal[o] = ssal[ci];
        acc[o]  = 0.f;
    }

    // ---- 11x11 bilateral, row-shared: each (row,dx) tap loaded ONCE,
    //      feeds up to 4 outputs. Output o consumes smem rows sy in [o, o+10].
    ROW(0, 0, 0);
    ROW(1, 0, 1);
    ROW(2, 0, 2);
    #pragma unroll 2
    for (int sy = 3; sy <= 10; sy++) ROW(sy, 0, 3);
    ROW(11, 1, 3);
    ROW(12, 2, 3);
    ROW(13, 3, 3);

    float loss_t = 0.f, mask_t = 0.f;
    #pragma unroll
    for (int o = 0; o < 4; o++) {
        loss_t = fmaf(mask[o], acc[o], loss_t);
        mask_t += mask[o];
    }

    // ---- block reduction: warp shuffle -> smem -> 2 atomics ----
    #pragma unroll
    for (int off = 16; off > 0; off >>= 1) {
        loss_t += __shfl_xor_sync(0xffffffffu, loss_t, off);
        mask_t += __shfl_xor_sync(0xffffffffu, mask_t, off);
    }
    __shared__ float red[16];
    const int wid = tid >> 5;
    const int lid = tid & 31;
    if (lid == 0) {
        red[wid]     = loss_t;
        red[8 + wid] = mask_t;
    }
    __syncthreads();
    if (tid == 0) {
        float L = 0.f, M = 0.f;
        #pragma unroll
        for (int i = 0; i < 8; i++) { L += red[i]; M += red[8 + i]; }
        atomicAdd(&g_acc[0], L);
        atomicAdd(&g_acc[1], M);
    }
}

__global__ void btm_finalize_kernel(float* __restrict__ out) {
    out[0] = g_acc[0] / (g_acc[1] + 1e-6f);
}

extern "C" void kernel_launch(void* const* d_in, const int* in_sizes, int n_in,
                              void* d_out, int out_size) {
    const float* pred = (const float*)d_in[0];   // (8,1,352,352)
    const float* feat = (const float*)d_in[1];   // (8,3,352,352)
    float* out = (float*)d_out;                  // scalar

    btm_init_kernel<<<1, 1>>>();

    dim3 grid(WW / TILE, HH / TILE, NIMG);       // (11, 11, 8)
    dim3 block(32, 8);
    btm_main_kernel<<<grid, block>>>(pred, feat);

    btm_finalize_kernel<<<1, 1>>>(out);
}